// round 13
// baseline (speedup 1.0000x reference)
#include <cuda_runtime.h>
#include <cfloat>

#define NB    2
#define CC    256
#define HH    64
#define WW    64
#define KK    128
#define PH    7
#define PW    7

// NHWC scratch: [2, 64, 64, 256] floats = 8.4 MB
__device__ float g_xt[NB * HH * WW * CC];

// ---------------- Kernel 1: NCHW -> NHWC transpose ----------------
__global__ __launch_bounds__(256) void transpose_kernel(const float* __restrict__ x)
{
    __shared__ float tile[32][33];
    int b   = blockIdx.z;
    int hw0 = blockIdx.x * 32;
    int c0  = blockIdx.y * 32;

    const float* src = x    + (size_t)b * CC * (HH * WW);
    float*       dst = g_xt + (size_t)b * (HH * WW) * CC;

    #pragma unroll
    for (int i = 0; i < 4; ++i) {
        int c = c0 + threadIdx.y + i * 8;
        tile[threadIdx.y + i * 8][threadIdx.x] = src[(size_t)c * (HH * WW) + hw0 + threadIdx.x];
    }
    __syncthreads();
    #pragma unroll
    for (int i = 0; i < 4; ++i) {
        int hw = hw0 + threadIdx.y + i * 8;
        dst[(size_t)hw * CC + c0 + threadIdx.x] = tile[threadIdx.x][threadIdx.y + i * 8];
    }
}

// ---------------- Kernel 2: ROI max-pool, warp-per-bin, depth-4 prefetch ----------------
// Block = (k, cg in {0,1}, bin-row i). 7 warps; warp j pools bin (i,j).
// Lane = float4 channel quad -> warp covers 128 channels; 1 LDG.128 per pixel.
// Flattened pixel loop with a 4-deep rotating prefetch buffer: consume load t,
// issue load t+4. MLP=4 with NO duplicated traffic (R12's mistake).
__global__ __launch_bounds__(224, 7) void roipool_pipe_kernel(
    const float* __restrict__ rois,  // [K, 5]
    float* __restrict__ out)         // [K, C, 7, 7]
{
    __shared__ float stage[128 * PW];  // [c_local][j]

    int bid = blockIdx.x;
    int k   = bid / (2 * PH);
    int rem = bid - k * (2 * PH);
    int cg  = rem / PH;          // 128-channel half
    int i   = rem - cg * PH;     // bin row
    int j    = threadIdx.x >> 5; // warp -> bin col
    int lane = threadIdx.x & 31;

    const float* r = rois + k * 5;
    int b  = (int)r[0];
    // IEEE RN multiply (0.0625 exact), round half-to-even like jnp.round
    int x1 = (int)rintf(__fmul_rn(r[1], 0.0625f));
    int y1 = (int)rintf(__fmul_rn(r[2], 0.0625f));
    int x2 = (int)rintf(__fmul_rn(r[3], 0.0625f));
    int y2 = (int)rintf(__fmul_rn(r[4], 0.0625f));

    int roi_w = max(x2 - x1 + 1, 1);
    int roi_h = max(y2 - y1 + 1, 1);

    // XLA rewrites (x / 7) -> x * RN(1/7); RN(1/7) = 0x3E124925
    const float RECIP7 = __int_as_float(0x3E124925);
    float bw = __fmul_rn((float)roi_w, RECIP7);
    float bh = __fmul_rn((float)roi_h, RECIP7);

    int hs = min(max((int)floorf(__fmul_rn((float)i,       bh)) + y1, 0), HH);
    int he = min(max((int)ceilf (__fmul_rn((float)(i + 1), bh)) + y1, 0), HH);
    int ws = min(max((int)floorf(__fmul_rn((float)j,       bw)) + x1, 0), WW);
    int we = min(max((int)ceilf (__fmul_rn((float)(j + 1), bw)) + x1, 0), WW);

    float4 acc = make_float4(0.f, 0.f, 0.f, 0.f);
    if (hs < he && ws < we) {
        acc = make_float4(-FLT_MAX, -FLT_MAX, -FLT_MAX, -FLT_MAX);
        const float4* fb = (const float4*)(g_xt + (size_t)b * (HH * WW) * CC)
                           + cg * 32 + lane;
        int nw   = we - ws;
        int npix = (he - hs) * nw;

        // Prefetch cursor (saturates at last pixel once exhausted; those
        // clamped loads are L1 hits and never consumed)
        int hp = hs, wp = ws;
        const float4* pp = fb + (size_t)(hs * WW + ws) * 64;

        float4 buf[4];
        #pragma unroll
        for (int s = 0; s < 4; ++s) {
            buf[s] = __ldg(pp);
            // advance
            if (++wp == we) {
                if (++hp < he) { wp = ws; pp += (size_t)(WW - nw + 1) * 64; }
                else           { --wp; --hp; }           // saturate
            } else {
                pp += 64;
            }
        }

        #pragma unroll 4
        for (int t = 0; t < npix; ++t) {
            float4 v = buf[t & 3];
            acc.x = fmaxf(acc.x, v.x);
            acc.y = fmaxf(acc.y, v.y);
            acc.z = fmaxf(acc.z, v.z);
            acc.w = fmaxf(acc.w, v.w);
            buf[t & 3] = __ldg(pp);
            if (++wp == we) {
                if (++hp < he) { wp = ws; pp += (size_t)(WW - nw + 1) * 64; }
                else           { --wp; --hp; }           // saturate
            } else {
                pp += 64;
            }
        }
    }

    int c0 = lane * 4;
    stage[(c0 + 0) * PW + j] = acc.x;
    stage[(c0 + 1) * PW + j] = acc.y;
    stage[(c0 + 2) * PW + j] = acc.z;
    stage[(c0 + 3) * PW + j] = acc.w;
    __syncthreads();

    // out[k, cg*128 + c, i, j]; channel stride = 49
    float* o = out + (size_t)k * (CC * PH * PW) + (size_t)cg * 128 * (PH * PW) + i * PW;
    for (int idx = threadIdx.x; idx < 128 * PW; idx += 224) {
        int c  = idx / PW;
        int jj = idx - c * PW;
        o[(size_t)c * (PH * PW) + jj] = stage[idx];
    }
}

extern "C" void kernel_launch(void* const* d_in, const int* in_sizes, int n_in,
                              void* d_out, int out_size)
{
    const float* x    = (const float*)d_in[0];
    const float* rois = (const float*)d_in[1];
    if (n_in >= 2 && in_sizes[0] < in_sizes[1]) {
        x    = (const float*)d_in[1];
        rois = (const float*)d_in[0];
    }
    float* out = (float*)d_out;

    dim3 tgrid(HH * WW / 32, CC / 32, NB);   // (128, 8, 2)
    dim3 tblk(32, 8);
    transpose_kernel<<<tgrid, tblk>>>(x);

    roipool_pipe_kernel<<<KK * 2 * PH, 224>>>(rois, out);  // 1792 blocks
}

// round 14
// speedup vs baseline: 1.0842x; 1.0842x over previous
#include <cuda_runtime.h>
#include <cfloat>

#define NB    2
#define CC    256
#define HH    64
#define WW    64
#define KK    128
#define PH    7
#define PW    7

// NHWC scratch: [2, 64, 64, 256] floats = 8.4 MB
__device__ float g_xt[NB * HH * WW * CC];

// ---------------- Kernel 1: NCHW -> NHWC transpose ----------------
__global__ __launch_bounds__(256) void transpose_kernel(const float* __restrict__ x)
{
    __shared__ float tile[32][33];
    int b   = blockIdx.z;
    int hw0 = blockIdx.x * 32;
    int c0  = blockIdx.y * 32;

    const float* src = x    + (size_t)b * CC * (HH * WW);
    float*       dst = g_xt + (size_t)b * (HH * WW) * CC;

    #pragma unroll
    for (int i = 0; i < 4; ++i) {
        int c = c0 + threadIdx.y + i * 8;
        tile[threadIdx.y + i * 8][threadIdx.x] = src[(size_t)c * (HH * WW) + hw0 + threadIdx.x];
    }
    __syncthreads();
    #pragma unroll
    for (int i = 0; i < 4; ++i) {
        int hw = hw0 + threadIdx.y + i * 8;
        dst[(size_t)hw * CC + c0 + threadIdx.x] = tile[threadIdx.x][threadIdx.y + i * 8];
    }
}

// ---------------- Kernel 2: ROI max-pool ----------------
// Block = (k, cg in {0,1}, bin-row i). 28 warps = (bin-col j, row-quarter q).
// Warp (j,q) pools rows hs+q, hs+q+4, ... of bin (i,j) — strided, disjoint,
// NO duplicated loads. Lane = float4 channel quad (128 channels per warp).
// Inner w-loop identical to the proven R9 kernel (unroll 2, 2 indep loads).
__global__ __launch_bounds__(896, 2) void roipool_hsplit_kernel(
    const float* __restrict__ rois,  // [K, 5]
    float* __restrict__ out)         // [K, C, 7, 7]
{
    __shared__ float stage[4][PW][128];  // [q][j][c_local] = 14 KB

    int bid = blockIdx.x;
    int k   = bid / (2 * PH);
    int rem = bid - k * (2 * PH);
    int cg  = rem / PH;          // 128-channel half
    int i   = rem - cg * PH;     // bin row
    int warp = threadIdx.x >> 5; // 0..27
    int lane = threadIdx.x & 31;
    int j    = warp >> 2;        // bin col 0..6
    int q    = warp & 3;         // row quarter

    const float* r = rois + k * 5;
    int b  = (int)r[0];
    // IEEE RN multiply (0.0625 exact), round half-to-even like jnp.round
    int x1 = (int)rintf(__fmul_rn(r[1], 0.0625f));
    int y1 = (int)rintf(__fmul_rn(r[2], 0.0625f));
    int x2 = (int)rintf(__fmul_rn(r[3], 0.0625f));
    int y2 = (int)rintf(__fmul_rn(r[4], 0.0625f));

    int roi_w = max(x2 - x1 + 1, 1);
    int roi_h = max(y2 - y1 + 1, 1);

    // XLA rewrites (x / 7) -> x * RN(1/7); RN(1/7) = 0x3E124925
    const float RECIP7 = __int_as_float(0x3E124925);
    float bw = __fmul_rn((float)roi_w, RECIP7);
    float bh = __fmul_rn((float)roi_h, RECIP7);

    int hs = min(max((int)floorf(__fmul_rn((float)i,       bh)) + y1, 0), HH);
    int he = min(max((int)ceilf (__fmul_rn((float)(i + 1), bh)) + y1, 0), HH);
    int ws = min(max((int)floorf(__fmul_rn((float)j,       bw)) + x1, 0), WW);
    int we = min(max((int)ceilf (__fmul_rn((float)(j + 1), bw)) + x1, 0), WW);

    float4 acc = make_float4(-FLT_MAX, -FLT_MAX, -FLT_MAX, -FLT_MAX);
    if (ws < we) {
        const float4* base = (const float4*)(g_xt + (size_t)b * (HH * WW) * CC + cg * 128) + lane;
        for (int h = hs + q; h < he; h += 4) {
            const float4* rowp = base + (size_t)(h * WW) * 64;
            int w = ws;
            for (; w + 1 < we; w += 2) {
                float4 v0 = __ldg(rowp + (size_t)w       * 64);
                float4 v1 = __ldg(rowp + (size_t)(w + 1) * 64);
                acc.x = fmaxf(acc.x, fmaxf(v0.x, v1.x));
                acc.y = fmaxf(acc.y, fmaxf(v0.y, v1.y));
                acc.z = fmaxf(acc.z, fmaxf(v0.z, v1.z));
                acc.w = fmaxf(acc.w, fmaxf(v0.w, v1.w));
            }
            if (w < we) {
                float4 v = __ldg(rowp + (size_t)w * 64);
                acc.x = fmaxf(acc.x, v.x);
                acc.y = fmaxf(acc.y, v.y);
                acc.z = fmaxf(acc.z, v.z);
                acc.w = fmaxf(acc.w, v.w);
            }
        }
    }
    ((float4*)&stage[q][j][0])[lane] = acc;
    __syncthreads();

    // Combine quarters + empty handling + store.
    // 896 outputs (128 ch x 7 j), one per thread.
    int t  = threadIdx.x;
    int c  = t / PW;            // 0..127
    int j2 = t - c * PW;        // 0..6
    int ws2 = min(max((int)floorf(__fmul_rn((float)j2,       bw)) + x1, 0), WW);
    int we2 = min(max((int)ceilf (__fmul_rn((float)(j2 + 1), bw)) + x1, 0), WW);
    float v = 0.0f;
    if (hs < he && ws2 < we2)
        v = fmaxf(fmaxf(stage[0][j2][c], stage[1][j2][c]),
                  fmaxf(stage[2][j2][c], stage[3][j2][c]));
    out[(size_t)k * (CC * PH * PW) + (size_t)(cg * 128 + c) * (PH * PW) + i * PW + j2] = v;
}

extern "C" void kernel_launch(void* const* d_in, const int* in_sizes, int n_in,
                              void* d_out, int out_size)
{
    const float* x    = (const float*)d_in[0];
    const float* rois = (const float*)d_in[1];
    if (n_in >= 2 && in_sizes[0] < in_sizes[1]) {
        x    = (const float*)d_in[1];
        rois = (const float*)d_in[0];
    }
    float* out = (float*)d_out;

    dim3 tgrid(HH * WW / 32, CC / 32, NB);   // (128, 8, 2)
    dim3 tblk(32, 8);
    transpose_kernel<<<tgrid, tblk>>>(x);

    roipool_hsplit_kernel<<<KK * 2 * PH, 896>>>(rois, out);  // 1792 blocks
}

// round 15
// speedup vs baseline: 1.9051x; 1.7571x over previous
#include <cuda_runtime.h>
#include <cfloat>

#define NB    2
#define CC    256
#define HH    64
#define WW    64
#define KK    128
#define PH    7
#define PW    7

// NHWC scratch: [2, 64, 64, 256] floats = 8.4 MB
__device__ float g_xt[NB * HH * WW * CC];

// ---------------- Kernel 1: NCHW -> NHWC transpose ----------------
__global__ __launch_bounds__(256) void transpose_kernel(const float* __restrict__ x)
{
    __shared__ float tile[32][33];
    int b   = blockIdx.z;
    int hw0 = blockIdx.x * 32;
    int c0  = blockIdx.y * 32;

    const float* src = x    + (size_t)b * CC * (HH * WW);
    float*       dst = g_xt + (size_t)b * (HH * WW) * CC;

    #pragma unroll
    for (int i = 0; i < 4; ++i) {
        int c = c0 + threadIdx.y + i * 8;
        tile[threadIdx.y + i * 8][threadIdx.x] = src[(size_t)c * (HH * WW) + hw0 + threadIdx.x];
    }
    __syncthreads();
    #pragma unroll
    for (int i = 0; i < 4; ++i) {
        int hw = hw0 + threadIdx.y + i * 8;
        dst[(size_t)hw * CC + c0 + threadIdx.x] = tile[threadIdx.x][threadIdx.y + i * 8];
    }
}

// ---------------- Kernel 2: ROI max-pool (R9 shape, row-pair interleave) ----------------
// Block = (k, cg in {0,1}, bin-row i). 7 warps; warp j pools bin (i,j).
// Lane = float4 channel quad -> warp covers 128 channels, 1 LDG.128/pixel.
// Rows processed in PAIRS (2 row pointers) x w-unroll-2 -> 4 independent
// loads per iteration, disjoint pixels, zero duplicated traffic.
__global__ __launch_bounds__(224) void roipool_rowpair_kernel(
    const float* __restrict__ rois,  // [K, 5]
    float* __restrict__ out)         // [K, C, 7, 7]
{
    __shared__ float stage[128 * PW];  // [c_local][j]

    int bid = blockIdx.x;
    int k   = bid / (2 * PH);
    int rem = bid - k * (2 * PH);
    int cg  = rem / PH;          // 128-channel half
    int i   = rem - cg * PH;     // bin row
    int j    = threadIdx.x >> 5; // warp -> bin col
    int lane = threadIdx.x & 31;

    const float* r = rois + k * 5;
    int b  = (int)r[0];
    // IEEE RN multiply (0.0625 exact), round half-to-even like jnp.round
    int x1 = (int)rintf(__fmul_rn(r[1], 0.0625f));
    int y1 = (int)rintf(__fmul_rn(r[2], 0.0625f));
    int x2 = (int)rintf(__fmul_rn(r[3], 0.0625f));
    int y2 = (int)rintf(__fmul_rn(r[4], 0.0625f));

    int roi_w = max(x2 - x1 + 1, 1);
    int roi_h = max(y2 - y1 + 1, 1);

    // XLA rewrites (x / 7) -> x * RN(1/7); RN(1/7) = 0x3E124925
    const float RECIP7 = __int_as_float(0x3E124925);
    float bw = __fmul_rn((float)roi_w, RECIP7);
    float bh = __fmul_rn((float)roi_h, RECIP7);

    int hs = min(max((int)floorf(__fmul_rn((float)i,       bh)) + y1, 0), HH);
    int he = min(max((int)ceilf (__fmul_rn((float)(i + 1), bh)) + y1, 0), HH);
    int ws = min(max((int)floorf(__fmul_rn((float)j,       bw)) + x1, 0), WW);
    int we = min(max((int)ceilf (__fmul_rn((float)(j + 1), bw)) + x1, 0), WW);

    float4 acc = make_float4(0.f, 0.f, 0.f, 0.f);
    if (hs < he && ws < we) {
        acc = make_float4(-FLT_MAX, -FLT_MAX, -FLT_MAX, -FLT_MAX);
        const float4* base = (const float4*)(g_xt + (size_t)b * (HH * WW) * CC + cg * 128) + lane;

        int h = hs;
        for (; h + 1 < he; h += 2) {
            const float4* r0 = base + (size_t)(h * WW) * 64;
            const float4* r1 = r0 + (size_t)WW * 64;
            int w = ws;
            for (; w + 1 < we; w += 2) {
                float4 v0 = __ldg(r0 + (size_t)w       * 64);
                float4 v1 = __ldg(r0 + (size_t)(w + 1) * 64);
                float4 v2 = __ldg(r1 + (size_t)w       * 64);
                float4 v3 = __ldg(r1 + (size_t)(w + 1) * 64);
                acc.x = fmaxf(fmaxf(acc.x, fmaxf(v0.x, v1.x)), fmaxf(v2.x, v3.x));
                acc.y = fmaxf(fmaxf(acc.y, fmaxf(v0.y, v1.y)), fmaxf(v2.y, v3.y));
                acc.z = fmaxf(fmaxf(acc.z, fmaxf(v0.z, v1.z)), fmaxf(v2.z, v3.z));
                acc.w = fmaxf(fmaxf(acc.w, fmaxf(v0.w, v1.w)), fmaxf(v2.w, v3.w));
            }
            if (w < we) {
                float4 v0 = __ldg(r0 + (size_t)w * 64);
                float4 v1 = __ldg(r1 + (size_t)w * 64);
                acc.x = fmaxf(acc.x, fmaxf(v0.x, v1.x));
                acc.y = fmaxf(acc.y, fmaxf(v0.y, v1.y));
                acc.z = fmaxf(acc.z, fmaxf(v0.z, v1.z));
                acc.w = fmaxf(acc.w, fmaxf(v0.w, v1.w));
            }
        }
        if (h < he) {  // final odd row (R9 path)
            const float4* r0 = base + (size_t)(h * WW) * 64;
            int w = ws;
            for (; w + 1 < we; w += 2) {
                float4 v0 = __ldg(r0 + (size_t)w       * 64);
                float4 v1 = __ldg(r0 + (size_t)(w + 1) * 64);
                acc.x = fmaxf(acc.x, fmaxf(v0.x, v1.x));
                acc.y = fmaxf(acc.y, fmaxf(v0.y, v1.y));
                acc.z = fmaxf(acc.z, fmaxf(v0.z, v1.z));
                acc.w = fmaxf(acc.w, fmaxf(v0.w, v1.w));
            }
            if (w < we) {
                float4 v = __ldg(r0 + (size_t)w * 64);
                acc.x = fmaxf(acc.x, v.x);
                acc.y = fmaxf(acc.y, v.y);
                acc.z = fmaxf(acc.z, v.z);
                acc.w = fmaxf(acc.w, v.w);
            }
        }
    }

    int c0 = lane * 4;
    stage[(c0 + 0) * PW + j] = acc.x;
    stage[(c0 + 1) * PW + j] = acc.y;
    stage[(c0 + 2) * PW + j] = acc.z;
    stage[(c0 + 3) * PW + j] = acc.w;
    __syncthreads();

    // out[k, cg*128 + c, i, j]; channel stride = 49
    float* o = out + (size_t)k * (CC * PH * PW) + (size_t)cg * 128 * (PH * PW) + i * PW;
    for (int idx = threadIdx.x; idx < 128 * PW; idx += 224) {
        int c  = idx / PW;
        int jj = idx - c * PW;
        o[(size_t)c * (PH * PW) + jj] = stage[idx];
    }
}

extern "C" void kernel_launch(void* const* d_in, const int* in_sizes, int n_in,
                              void* d_out, int out_size)
{
    const float* x    = (const float*)d_in[0];
    const float* rois = (const float*)d_in[1];
    if (n_in >= 2 && in_sizes[0] < in_sizes[1]) {
        x    = (const float*)d_in[1];
        rois = (const float*)d_in[0];
    }
    float* out = (float*)d_out;

    dim3 tgrid(HH * WW / 32, CC / 32, NB);   // (128, 8, 2)
    dim3 tblk(32, 8);
    transpose_kernel<<<tgrid, tblk>>>(x);

    roipool_rowpair_kernel<<<KK * 2 * PH, 224>>>(rois, out);  // 1792 blocks
}